// round 15
// baseline (speedup 1.0000x reference)
#include <cuda_runtime.h>
#include <cuda_fp16.h>
#include <cstdint>

#define M_DIM 4096
#define N_DIM 32000
#define KP 68                          // padded row stride in half2 words
#define ROWB (KP * 4)                  // 272 bytes per padded row
#define BN 256
#define MSTEP 64
#define B_BYTES (BN * ROWB)            // 69632
#define A_BYTES (MSTEP * ROWB)         // 17408
#define SM_A0 B_BYTES
#define SM_A1 (B_BYTES + A_BYTES)
#define SM_MB (B_BYTES + 2 * A_BYTES)  // 104448 (two 8B mbarriers)
#define SM_TOTAL (SM_MB + 16)
#define NS 32                          // M-steps per CTA (2048 rows)

// Device scratch: fp16, PADDED rows (stride 68 words) so tiles are linearly
// bulk-copyable into the conflict-free KP=68 smem layout.
__device__ uint32_t g_Ah[M_DIM * KP];    // 1.1 MB
__device__ uint32_t g_Wh[N_DIM * KP];    // 8.7 MB
__device__ int g_stride;

__device__ __forceinline__ uint32_t packh(float lo, float hi) {
    __half2 h = __floats2half2_rn(lo, hi);
    return *reinterpret_cast<uint32_t*>(&h);
}
__device__ __forceinline__ void mbar_init(uint32_t mb, uint32_t cnt) {
    asm volatile("mbarrier.init.shared.b64 [%0], %1;" :: "r"(mb), "r"(cnt) : "memory");
}
__device__ __forceinline__ void mbar_expect(uint32_t mb, uint32_t bytes) {
    asm volatile("mbarrier.arrive.expect_tx.shared.b64 _, [%0], %1;"
                 :: "r"(mb), "r"(bytes) : "memory");
}
__device__ __forceinline__ void bulk_g2s(uint32_t dst, const void* src,
                                         uint32_t bytes, uint32_t mb) {
    asm volatile("cp.async.bulk.shared::cta.global.mbarrier::complete_tx::bytes "
                 "[%0], [%1], %2, [%3];"
                 :: "r"(dst), "l"(src), "r"(bytes), "r"(mb) : "memory");
}
__device__ __forceinline__ void mbar_wait(uint32_t mb, uint32_t ph) {
    uint32_t done;
    asm volatile(
        "{\n\t.reg .pred p;\n\t"
        "mbarrier.try_wait.parity.shared.b64 p, [%1], %2;\n\t"
        "selp.b32 %0, 1, 0, p;\n\t}"
        : "=r"(done) : "r"(mb), "r"(ph) : "memory");
    if (!done) {
        asm volatile(
            "{\n\t.reg .pred P1;\n\t"
            "WL%=:\n\t"
            "mbarrier.try_wait.parity.shared.b64 P1, [%0], %1;\n\t"
            "@P1 bra.uni WD%=;\n\t"
            "bra.uni WL%=;\n\t"
            "WD%=:\n\t}"
            :: "r"(mb), "r"(ph) : "memory");
    }
}

// ---------------------------------------------------------------------------
// Detect int64 vs int32 index tensor (odd 32-bit words all zero => int64).
// ---------------------------------------------------------------------------
__global__ void detect_kernel(const int* __restrict__ x32) {
    __shared__ int any;
    if (threadIdx.x == 0) any = 0;
    __syncthreads();
    int i = 1 + 2 * threadIdx.x;
    int v = x32[i] | x32[i + 512] | x32[i + 1024] | x32[i + 1536];
    if (v) any = 1;   // benign race
    __syncthreads();
    if (threadIdx.x == 0) g_stride = any ? 1 : 2;
}

// ---------------------------------------------------------------------------
// W -> fp16, padded rows.
// ---------------------------------------------------------------------------
__global__ void conv_w_kernel(const float4* __restrict__ W) {
    int i = blockIdx.x * 256 + threadIdx.x;   // 1,024,000 float4
    int n = i >> 5, c = i & 31;               // row, float4-within-row
    float4 v = W[(size_t)n * 32 + c];
    g_Wh[n * KP + c * 2]     = packh(v.x, v.y);
    g_Wh[n * KP + c * 2 + 1] = packh(v.z, v.w);
}

// ---------------------------------------------------------------------------
// CBOW gather-sum (padding_idx=0 skipped), fp16, padded rows.
// ---------------------------------------------------------------------------
__global__ void sum_emb_kernel(const int* __restrict__ x32,
                               const float4* __restrict__ emb) {
    int sample = blockIdx.x * 8 + (threadIdx.x >> 5);
    int v = threadIdx.x & 31;
    int stride = g_stride;
    float4 s = make_float4(0.f, 0.f, 0.f, 0.f);
#pragma unroll
    for (int c = 0; c < 8; c++) {
        int i = x32[(sample * 8 + c) * stride];
        if (i != 0) {
            float4 t = emb[i * 32 + v];
            s.x += t.x; s.y += t.y; s.z += t.z; s.w += t.w;
        }
    }
    g_Ah[sample * KP + v * 2]     = packh(s.x, s.y);
    g_Ah[sample * KP + v * 2 + 1] = packh(s.z, s.w);
}

// ---------------------------------------------------------------------------
// GEMM: out[M,N] = A[M,K] @ W[N,K]^T + b  (fp16 in, fp32 accumulate)
// grid (125, 2), 512 threads, 16 warps (2M x 8N), warp tile 32x32.
// B stripe (256 rows) bulk-copied to smem ONCE; 32 M-steps of 64 rows with
// double-buffered A tiles, each ONE cp.async.bulk (kills the per-16B LDGSTS
// issue tax that bounded every previous round). mbarrier expect_tx/parity.
// ---------------------------------------------------------------------------
__global__ void __launch_bounds__(512, 1)
gemm_kernel(const float* __restrict__ bias, float* __restrict__ out) {
    extern __shared__ unsigned smem[];
    unsigned* Bs = smem;                                  // [256][68]
    const uint32_t sb = (uint32_t)__cvta_generic_to_shared(smem);

    const int tid = threadIdx.x;
    const int bn = blockIdx.x * BN;
    const int m_base = blockIdx.y * (NS * MSTEP);

    if (tid == 0) {
        mbar_init(sb + SM_MB, 1);
        mbar_init(sb + SM_MB + 8, 1);
    }
    __syncthreads();
    if (tid == 0) {
        mbar_expect(sb + SM_MB, B_BYTES + A_BYTES);
        bulk_g2s(sb, (const char*)g_Wh + (size_t)bn * ROWB, B_BYTES, sb + SM_MB);
        bulk_g2s(sb + SM_A0, (const char*)g_Ah + (size_t)m_base * ROWB,
                 A_BYTES, sb + SM_MB);
        mbar_expect(sb + SM_MB + 8, A_BYTES);
        bulk_g2s(sb + SM_A1, (const char*)g_Ah + (size_t)(m_base + MSTEP) * ROWB,
                 A_BYTES, sb + SM_MB + 8);
    }

    const int lane = tid & 31;
    const int warp = tid >> 5;
    const int wm = (warp & 1) * 32;    // 2 warps along M
    const int wn = (warp >> 1) * 32;   // 8 warps along N
    const int g  = lane >> 2;          // 0..7
    const int tg = lane & 3;           // 0..3

    // hoist bias (constant across M-steps)
    float2 bb[4];
#pragma unroll
    for (int ni = 0; ni < 4; ni++)
        bb[ni] = *reinterpret_cast<const float2*>(bias + bn + wn + ni * 8 + 2 * tg);

    uint32_t ph[2] = {0u, 0u};

#pragma unroll 1
    for (int step = 0; step < NS; step++) {
        const int cur = step & 1;
        const uint32_t mb = sb + SM_MB + cur * 8;
        mbar_wait(mb, ph[cur]);
        ph[cur] ^= 1;

        const unsigned* As = smem + (SM_A0 + cur * A_BYTES) / 4;

        float acc[2][4][4];
#pragma unroll
        for (int mi = 0; mi < 2; mi++)
#pragma unroll
            for (int ni = 0; ni < 4; ni++)
#pragma unroll
                for (int r = 0; r < 4; r++) acc[mi][ni][r] = 0.f;

#pragma unroll
        for (int ks = 0; ks < 8; ks++) {
            const int k0w = ks * 8;
            unsigned a[2][4], b[4][2];
#pragma unroll
            for (int mi = 0; mi < 2; mi++) {
                int r0 = (wm + mi * 16 + g) * KP + k0w + tg;
                a[mi][0] = As[r0];
                a[mi][1] = As[r0 + 8 * KP];
                a[mi][2] = As[r0 + 4];
                a[mi][3] = As[r0 + 8 * KP + 4];
            }
#pragma unroll
            for (int ni = 0; ni < 4; ni++) {
                int c0 = (wn + ni * 8 + g) * KP + k0w + tg;
                b[ni][0] = Bs[c0];
                b[ni][1] = Bs[c0 + 4];
            }
#pragma unroll
            for (int mi = 0; mi < 2; mi++)
#pragma unroll
                for (int ni = 0; ni < 4; ni++)
                    asm volatile(
                        "mma.sync.aligned.m16n8k16.row.col.f32.f16.f16.f32 "
                        "{%0,%1,%2,%3}, {%4,%5,%6,%7}, {%8,%9}, {%0,%1,%2,%3};"
                        : "+f"(acc[mi][ni][0]), "+f"(acc[mi][ni][1]),
                          "+f"(acc[mi][ni][2]), "+f"(acc[mi][ni][3])
                        : "r"(a[mi][0]), "r"(a[mi][1]),
                          "r"(a[mi][2]), "r"(a[mi][3]),
                          "r"(b[ni][0]), "r"(b[ni][1]));
        }

        // all warps done reading buffer `cur` -> safe to refill it
        __syncthreads();
        if (step + 2 < NS && tid == 0) {
            mbar_expect(mb, A_BYTES);
            bulk_g2s(sb + SM_A0 + cur * A_BYTES,
                     (const char*)g_Ah + (size_t)(m_base + (step + 2) * MSTEP) * ROWB,
                     A_BYTES, mb);
        }

        // epilogue for this M-step (overlaps the in-flight refills)
        const int bm = m_base + step * MSTEP;
#pragma unroll
        for (int ni = 0; ni < 4; ni++) {
            int col = bn + wn + ni * 8 + 2 * tg;
#pragma unroll
            for (int mi = 0; mi < 2; mi++) {
                int row = bm + wm + mi * 16 + g;
                float2 v0 = make_float2(acc[mi][ni][0] + bb[ni].x,
                                        acc[mi][ni][1] + bb[ni].y);
                float2 v1 = make_float2(acc[mi][ni][2] + bb[ni].x,
                                        acc[mi][ni][3] + bb[ni].y);
                *reinterpret_cast<float2*>(out + (size_t)row * N_DIM + col) = v0;
                *reinterpret_cast<float2*>(out + (size_t)(row + 8) * N_DIM + col) = v1;
            }
        }
    }
}

// ---------------------------------------------------------------------------
extern "C" void kernel_launch(void* const* d_in, const int* in_sizes, int n_in,
                              void* d_out, int out_size) {
    const int*   x    = (const int*)d_in[0];
    const float* emb  = (const float*)d_in[1];
    const float* W    = (const float*)d_in[2];
    const float* bias = (const float*)d_in[3];
    float* out = (float*)d_out;

    (void)in_sizes; (void)n_in; (void)out_size;

    cudaFuncSetAttribute(gemm_kernel,
                         cudaFuncAttributeMaxDynamicSharedMemorySize, SM_TOTAL);

    detect_kernel<<<1, 256>>>(x);
    conv_w_kernel<<<4000, 256>>>((const float4*)W);
    sum_emb_kernel<<<M_DIM / 8, 256>>>(x, (const float4*)emb);

    dim3 grid(N_DIM / BN, 2);                  // (125, 2)
    gemm_kernel<<<grid, 512, SM_TOTAL>>>(bias, out);
}

// round 16
// speedup vs baseline: 1.1139x; 1.1139x over previous
#include <cuda_runtime.h>
#include <cuda_fp16.h>
#include <cstdint>

// Problem constants
#define M_DIM 4096
#define N_DIM 32000
#define K_DIM 128
#define BM 128
#define BN 128
#define KW 64    // K in 32-bit words (half2): 128 fp16 = 64 words
#define KP 68    // padded k-stride in words (68 % 32 == 4 -> conflict-free)

// Device scratch: fp16 copies, packed half2 per uint32
__device__ uint32_t g_Ah[M_DIM * KW];    // 1 MB
__device__ uint32_t g_Wh[N_DIM * KW];    // 8.2 MB
__device__ int g_stride;                 // 1 = int32 indices, 2 = int64

__device__ __forceinline__ uint32_t packh(float lo, float hi) {
    __half2 h = __floats2half2_rn(lo, hi);   // lo -> low half (first in memory)
    return *reinterpret_cast<uint32_t*>(&h);
}
__device__ __forceinline__ void cp16(uint32_t dst, const void* src) {
    asm volatile("cp.async.cg.shared.global [%0], [%1], 16;" :: "r"(dst), "l"(src));
}
template <int N> __device__ __forceinline__ void cp_wait() {
    asm volatile("cp.async.wait_group %0;" :: "n"(N));
}
__device__ __forceinline__ void ldsm4(unsigned& r0, unsigned& r1,
                                      unsigned& r2, unsigned& r3, uint32_t a) {
    asm volatile("ldmatrix.sync.aligned.m8n8.x4.shared.b16 {%0,%1,%2,%3}, [%4];"
                 : "=r"(r0), "=r"(r1), "=r"(r2), "=r"(r3) : "r"(a));
}

// ---------------------------------------------------------------------------
// Detect int64 vs int32 index tensor (odd 32-bit words all zero => int64).
// ---------------------------------------------------------------------------
__global__ void detect_kernel(const int* __restrict__ x32) {
    __shared__ int any;
    if (threadIdx.x == 0) any = 0;
    __syncthreads();
    int i = 1 + 2 * threadIdx.x;
    int v = x32[i] | x32[i + 512] | x32[i + 1024] | x32[i + 1536];
    if (v) any = 1;   // benign race
    __syncthreads();
    if (threadIdx.x == 0) g_stride = any ? 1 : 2;
}

// ---------------------------------------------------------------------------
// W -> fp16 (packed half2).
// ---------------------------------------------------------------------------
__global__ void conv_w_kernel(const float4* __restrict__ W) {
    int i = blockIdx.x * 256 + threadIdx.x;   // 1,024,000 float4
    float4 v = W[i];
    g_Wh[i * 2]     = packh(v.x, v.y);
    g_Wh[i * 2 + 1] = packh(v.z, v.w);
}

// ---------------------------------------------------------------------------
// CBOW gather-sum (padding_idx=0 skipped), fp16 output (packed half2).
// ---------------------------------------------------------------------------
__global__ void sum_emb_kernel(const int* __restrict__ x32,
                               const float4* __restrict__ emb) {
    int sample = blockIdx.x * 8 + (threadIdx.x >> 5);
    int v = threadIdx.x & 31;
    int stride = g_stride;
    float4 s = make_float4(0.f, 0.f, 0.f, 0.f);
#pragma unroll
    for (int c = 0; c < 8; c++) {
        int i = x32[(sample * 8 + c) * stride];
        if (i != 0) {
            float4 t = emb[i * 32 + v];
            s.x += t.x; s.y += t.y; s.z += t.z; s.w += t.w;
        }
    }
    int base = sample * KW + v * 2;
    g_Ah[base]     = packh(s.x, s.y);
    g_Ah[base + 1] = packh(s.z, s.w);
}

// ---------------------------------------------------------------------------
// GEMM: out[M,N] = A[M,K] @ W[N,K]^T + b   (fp16 in, fp32 accumulate)
// CTA 128x128, 256 threads, 8 warps (2M x 4N), warp tile 64x32.
// Fragments via ldmatrix.m8n8.x4: 6 LDSM per k16-step replaces 24 scalar
// LDS (the dominant non-HMMA instruction mass in R14). KP=68 keeps all
// ldmatrix phases bank-conflict-free (4r mod 32 distinct for r=0..7).
// Smem 69,632 B -> 2 CTAs/SM. 4-chunk cp.async K-pipeline.
// ---------------------------------------------------------------------------
__global__ void __launch_bounds__(256, 2)
gemm_kernel(const float* __restrict__ bias, float* __restrict__ out) {
    extern __shared__ unsigned smem[];
    const uint32_t sbase = (uint32_t)__cvta_generic_to_shared(smem);

    const int tid = threadIdx.x;
    const int bm = blockIdx.y * BM;
    const int bn = blockIdx.x * BN;

    // ---- issue all 4 K-chunk load groups (A + B per chunk) ----
    const uint4* Ag = reinterpret_cast<const uint4*>(g_Ah) + bm * 16;
    const uint4* Bg = reinterpret_cast<const uint4*>(g_Wh) + bn * 16;
#pragma unroll
    for (int c = 0; c < 4; c++) {
#pragma unroll
        for (int t = 0; t < 2; t++) {              // A: 128 rows x 4 uint4
            int idx = tid + t * 256;
            int row = idx >> 2, j = idx & 3;
            cp16(sbase + (row * KP + c * 16 + j * 4) * 4,
                 Ag + row * 16 + c * 4 + j);
        }
#pragma unroll
        for (int t = 0; t < 2; t++) {              // B: 128 rows x 4 uint4
            int idx = tid + t * 256;
            int row = idx >> 2, j = idx & 3;
            cp16(sbase + (BM * KP + row * KP + c * 16 + j * 4) * 4,
                 Bg + row * 16 + c * 4 + j);
        }
        asm volatile("cp.async.commit_group;" ::: "memory");
    }

    const int lane = tid & 31;
    const int warp = tid >> 5;
    const int wm = (warp & 1) * 64;    // 2 warps along M
    const int wn = (warp >> 1) * 32;   // 4 warps along N
    const int g  = lane >> 2;          // 0..7
    const int tg = lane & 3;           // 0..3

    // ldmatrix per-lane base addresses (t = lane>>3 selects the 8x8 tile)
    const int t8 = lane >> 3, l8 = lane & 7;
    // A x4 tile order: {rows+0 w0, rows+8 w0, rows+0 w4, rows+8 w4}
    const uint32_t abase = sbase +
        ((wm + (t8 & 1) * 8 + l8) * KP + (t8 >> 1) * 4) * 4;
    // B x4 tile order: {n+0 w0, n+0 w4, n+8 w0, n+8 w4}  (2 ni per ldsm)
    const uint32_t bbase = sbase +
        (BM * KP + (wn + (t8 >> 1) * 8 + l8) * KP + (t8 & 1) * 4) * 4;

    float acc[4][4][4];
#pragma unroll
    for (int mi = 0; mi < 4; mi++)
#pragma unroll
        for (int ni = 0; ni < 4; ni++)
#pragma unroll
            for (int r = 0; r < 4; r++) acc[mi][ni][r] = 0.f;

#pragma unroll
    for (int c = 0; c < 4; c++) {
        if (c == 0)      cp_wait<3>();
        else if (c == 1) cp_wait<2>();
        else if (c == 2) cp_wait<1>();
        else             cp_wait<0>();
        __syncthreads();

#pragma unroll
        for (int q = 0; q < 2; q++) {              // 2 k-steps of k16 per chunk
            const uint32_t koff = (c * 16 + q * 8) * 4;   // bytes
            unsigned a[4][4], b[2][4];
#pragma unroll
            for (int mi = 0; mi < 4; mi++)
                ldsm4(a[mi][0], a[mi][1], a[mi][2], a[mi][3],
                      abase + mi * (16 * KP * 4) + koff);
#pragma unroll
            for (int nj = 0; nj < 2; nj++)
                ldsm4(b[nj][0], b[nj][1], b[nj][2], b[nj][3],
                      bbase + nj * (16 * KP * 4) + koff);
#pragma unroll
            for (int mi = 0; mi < 4; mi++)
#pragma unroll
                for (int ni = 0; ni < 4; ni++) {
                    const unsigned b0 = b[ni >> 1][(ni & 1) * 2];
                    const unsigned b1 = b[ni >> 1][(ni & 1) * 2 + 1];
                    asm volatile(
                        "mma.sync.aligned.m16n8k16.row.col.f32.f16.f16.f32 "
                        "{%0,%1,%2,%3}, {%4,%5,%6,%7}, {%8,%9}, {%0,%1,%2,%3};"
                        : "+f"(acc[mi][ni][0]), "+f"(acc[mi][ni][1]),
                          "+f"(acc[mi][ni][2]), "+f"(acc[mi][ni][3])
                        : "r"(a[mi][0]), "r"(a[mi][1]),
                          "r"(a[mi][2]), "r"(a[mi][3]),
                          "r"(b0), "r"(b1));
                }
        }
    }

    // Epilogue: bias add + float2 stores. Tiles divide exactly.
#pragma unroll
    for (int ni = 0; ni < 4; ni++) {
        int col = bn + wn + ni * 8 + 2 * tg;
        float2 bb = *reinterpret_cast<const float2*>(bias + col);
#pragma unroll
        for (int mi = 0; mi < 4; mi++) {
            int row = bm + wm + mi * 16 + g;
            float2 v0 = make_float2(acc[mi][ni][0] + bb.x, acc[mi][ni][1] + bb.y);
            float2 v1 = make_float2(acc[mi][ni][2] + bb.x, acc[mi][ni][3] + bb.y);
            *reinterpret_cast<float2*>(out + (size_t)row * N_DIM + col) = v0;
            *reinterpret_cast<float2*>(out + (size_t)(row + 8) * N_DIM + col) = v1;
        }
    }
}

// ---------------------------------------------------------------------------
extern "C" void kernel_launch(void* const* d_in, const int* in_sizes, int n_in,
                              void* d_out, int out_size) {
    const int*   x    = (const int*)d_in[0];
    const float* emb  = (const float*)d_in[1];
    const float* W    = (const float*)d_in[2];
    const float* bias = (const float*)d_in[3];
    float* out = (float*)d_out;

    (void)in_sizes; (void)n_in; (void)out_size;

    static const int smem_bytes = (BM + BN) * KP * 4;   // 69,632 B -> 2 CTAs/SM
    cudaFuncSetAttribute(gemm_kernel,
                         cudaFuncAttributeMaxDynamicSharedMemorySize,
                         smem_bytes);

    detect_kernel<<<1, 256>>>(x);
    conv_w_kernel<<<N_DIM * K_DIM / 4 / 256, 256>>>((const float4*)W);
    sum_emb_kernel<<<M_DIM / 8, 256>>>(x, (const float4*)emb);

    dim3 grid(N_DIM / BN, M_DIM / BM);                  // (250, 32)
    gemm_kernel<<<grid, 256, smem_bytes>>>(bias, out);
}